// round 9
// baseline (speedup 1.0000x reference)
#include <cuda_runtime.h>
#include <cuda_bf16.h>
#include <math.h>
#include <stdint.h>

// ===========================================================================
// QueryEmbedding — embed (fused) + 2 bf16-split GEMMs via mma.sync (HMMA)
//   M=32768, EMB=768, HID=3072
//   GEMM: D = A_hi*B_hi + A_hi*B_lo + A_lo*B_hi   (bf16 in, fp32 accum)
//   NOTE: tcgen05 is unavailable (harness PTX target is sm_103, not sm_103a),
//   so we use the base-ISA mma.sync.m16n8k16 path with ldmatrix + cp.async.
// ===========================================================================

#define M_TOTAL   32768
#define EMB       768
#define HID       3072
#define BQ        16

// ---------------- device scratch (no allocs allowed) ----------------------
__device__ __align__(16) __nv_bfloat16 g_x_hi [(size_t)M_TOTAL * EMB];
__device__ __align__(16) __nv_bfloat16 g_x_lo [(size_t)M_TOTAL * EMB];
__device__ __align__(16) __nv_bfloat16 g_h_hi [(size_t)M_TOTAL * HID];
__device__ __align__(16) __nv_bfloat16 g_h_lo [(size_t)M_TOTAL * HID];
__device__ __align__(16) __nv_bfloat16 g_w1_hi[(size_t)HID * EMB];   // [N=3072][K=768]
__device__ __align__(16) __nv_bfloat16 g_w1_lo[(size_t)HID * EMB];
__device__ __align__(16) __nv_bfloat16 g_w2_hi[(size_t)EMB * HID];   // [N=768][K=3072]
__device__ __align__(16) __nv_bfloat16 g_w2_lo[(size_t)EMB * HID];

__device__ __forceinline__ float gelu_exact(float x) {
    return 0.5f * x * (1.0f + erff(x * 0.70710678118654752440f));
}

// ---------------- PTX helpers ----------------------------------------------
__device__ __forceinline__ uint32_t smem_u32(const void* p) {
    uint32_t a;
    asm("{ .reg .u64 t; cvta.to.shared.u64 t, %1; cvt.u32.u64 %0, t; }"
        : "=r"(a) : "l"(p));
    return a;
}

__device__ __forceinline__ void cp_async16(uint32_t saddr, const void* gaddr) {
    asm volatile("cp.async.cg.shared.global [%0], [%1], 16;"
                 :: "r"(saddr), "l"(gaddr) : "memory");
}
__device__ __forceinline__ void cp_commit() {
    asm volatile("cp.async.commit_group;" ::: "memory");
}
__device__ __forceinline__ void cp_wait1() {
    asm volatile("cp.async.wait_group 1;" ::: "memory");
}
__device__ __forceinline__ void cp_wait0() {
    asm volatile("cp.async.wait_group 0;" ::: "memory");
}

__device__ __forceinline__ void ldmx4(uint32_t* r, uint32_t addr) {
    asm volatile("ldmatrix.sync.aligned.m8n8.x4.shared.b16 {%0,%1,%2,%3}, [%4];"
                 : "=r"(r[0]), "=r"(r[1]), "=r"(r[2]), "=r"(r[3]) : "r"(addr));
}

__device__ __forceinline__ void mma_bf16(float* d, const uint32_t* a,
                                         uint32_t b0, uint32_t b1) {
    asm volatile(
        "mma.sync.aligned.m16n8k16.row.col.f32.bf16.bf16.f32 "
        "{%0,%1,%2,%3}, {%4,%5,%6,%7}, {%8,%9}, {%0,%1,%2,%3};"
        : "+f"(d[0]), "+f"(d[1]), "+f"(d[2]), "+f"(d[3])
        : "r"(a[0]), "r"(a[1]), "r"(a[2]), "r"(a[3]), "r"(b0), "r"(b1));
}

// ---------------------------------------------------------------------------
// Embed kernel: x = token1..token5 per query, emitted as bf16 hi/lo
// ---------------------------------------------------------------------------
__global__ __launch_bounds__(256)
void embed_kernel(const float* __restrict__ query,
                  const float* __restrict__ images,
                  const float* __restrict__ uv_w,
                  const float* __restrict__ uv_b,
                  const float* __restrict__ t_src_emb,
                  const float* __restrict__ t_tgt_emb,
                  const float* __restrict__ t_cam_emb,
                  const float* __restrict__ pm_w1,
                  const float* __restrict__ pm_b1,
                  const float* __restrict__ pm_w2,
                  const float* __restrict__ pm_b2,
                  int nPerB,
                  __nv_bfloat16* __restrict__ x_hi,
                  __nv_bfloat16* __restrict__ x_lo)
{
    __shared__ float s_feat[BQ][40];
    __shared__ float s_patch[BQ][27];
    __shared__ float s_h1[BQ][108];
    __shared__ int   s_src[BQ], s_tgt[BQ], s_cam[BQ], s_x[BQ], s_y[BQ];

    const int tid = threadIdx.x;
    const int q0  = blockIdx.x * BQ;
    const float TWO_PI = 6.283185307179586476925f;

    if (tid < BQ) {
        const float* qp = query + (size_t)(q0 + tid) * 5;
        float u = fminf(fmaxf(qp[0], 0.0f), 1.0f);
        float v = fminf(fmaxf(qp[1], 0.0f), 1.0f);
        s_src[tid] = min(max(__float2int_rn(qp[2]), 0), 47);
        s_tgt[tid] = min(max(__float2int_rn(qp[3]), 0), 47);
        s_cam[tid] = min(max(__float2int_rn(qp[4]), 0), 47);
        s_x[tid] = min(max(__float2int_rn(u * 255.0f), 0), 255);
        s_y[tid] = min(max(__float2int_rn(v * 255.0f), 0), 255);

        float f = 1.0f;
        #pragma unroll
        for (int k = 0; k < 10; k++) {
            float au = u * f; au = (au - floorf(au)) * TWO_PI;
            float av = v * f; av = (av - floorf(av)) * TWO_PI;
            s_feat[tid][k]      = sinf(au);
            s_feat[tid][10 + k] = cosf(au);
            s_feat[tid][20 + k] = sinf(av);
            s_feat[tid][30 + k] = cosf(av);
            f *= 2.0f;
        }
    }
    __syncthreads();

    for (int i = tid; i < BQ * 27; i += 256) {
        int q  = i / 27;
        int r  = i - q * 27;
        int c  = r / 9;
        int rem = r - c * 9;
        int dy = rem / 3;
        int dx = rem - dy * 3;
        int yy = min(max(s_y[q] + dy - 1, 0), 255);
        int xx = min(max(s_x[q] + dx - 1, 0), 255);
        int b  = (q0 + q) / nPerB;
        size_t idx = (((size_t)(b * 3 + c) * 48 + (size_t)s_src[q]) * 65536)
                     + (size_t)yy * 256 + (size_t)xx;
        s_patch[q][r] = images[idx];
    }
    __syncthreads();

    for (int i = tid; i < BQ * 108; i += 256) {
        int q = i / 108;
        int j = i - q * 108;
        float acc = pm_b1[j];
        #pragma unroll
        for (int k = 0; k < 27; k++)
            acc += s_patch[q][k] * pm_w1[k * 108 + j];
        s_h1[q][j] = gelu_exact(acc);
    }
    __syncthreads();

    float acc[BQ][3];
    #pragma unroll
    for (int jj = 0; jj < 3; jj++) {
        int j = jj * 256 + tid;
        float base = uv_b[j] + pm_b2[j];
        #pragma unroll
        for (int q = 0; q < BQ; q++) {
            acc[q][jj] = base
                       + t_src_emb[s_src[q] * EMB + j]
                       + t_tgt_emb[s_tgt[q] * EMB + j]
                       + t_cam_emb[s_cam[q] * EMB + j];
        }
    }

    #pragma unroll 1
    for (int k = 0; k < 40; k++) {
        float w0 = uv_w[k * EMB + tid];
        float w1 = uv_w[k * EMB + 256 + tid];
        float w2 = uv_w[k * EMB + 512 + tid];
        #pragma unroll
        for (int q = 0; q < BQ; q++) {
            float f = s_feat[q][k];
            acc[q][0] += f * w0;
            acc[q][1] += f * w1;
            acc[q][2] += f * w2;
        }
    }

    #pragma unroll 1
    for (int k = 0; k < 108; k++) {
        float w0 = pm_w2[k * EMB + tid];
        float w1 = pm_w2[k * EMB + 256 + tid];
        float w2 = pm_w2[k * EMB + 512 + tid];
        #pragma unroll
        for (int q = 0; q < BQ; q++) {
            float h = s_h1[q][k];
            acc[q][0] += h * w0;
            acc[q][1] += h * w1;
            acc[q][2] += h * w2;
        }
    }

    #pragma unroll
    for (int q = 0; q < BQ; q++) {
        size_t base = (size_t)(q0 + q) * EMB;
        #pragma unroll
        for (int jj = 0; jj < 3; jj++) {
            float v = acc[q][jj];
            __nv_bfloat16 h = __float2bfloat16(v);
            x_hi[base + jj * 256 + tid] = h;
            x_lo[base + jj * 256 + tid] = __float2bfloat16(v - __bfloat162float(h));
        }
    }
}

// ---------------------------------------------------------------------------
// Weight transpose + hi/lo split:  in[K][N] fp32  ->  out[N][K] bf16 hi/lo
// ---------------------------------------------------------------------------
__global__ __launch_bounds__(256)
void transpose_split_kernel(const float* __restrict__ in,
                            __nv_bfloat16* __restrict__ hi,
                            __nv_bfloat16* __restrict__ lo,
                            int K, int N)
{
    __shared__ float t[32][33];
    const int n0 = blockIdx.x * 32;
    const int k0 = blockIdx.y * 32;
    const int tx = threadIdx.x;   // 0..31
    const int ty = threadIdx.y;   // 0..7

    #pragma unroll
    for (int r = ty; r < 32; r += 8)
        t[r][tx] = in[(size_t)(k0 + r) * N + n0 + tx];
    __syncthreads();

    #pragma unroll
    for (int r = ty; r < 32; r += 8) {
        float v = t[tx][r];  // in[k0+tx][n0+r]
        __nv_bfloat16 h = __float2bfloat16(v);
        size_t o = (size_t)(n0 + r) * K + k0 + tx;
        hi[o] = h;
        lo[o] = __float2bfloat16(v - __bfloat162float(h));
    }
}

// ---------------------------------------------------------------------------
// HMMA GEMM:  C(128x128 tile) = A(MxK) @ B^T(NtotxK), bf16 3-term split.
//   A, B stored row-major [rows][K] bf16 (hi and lo planes).
//   GELU=true : out = gelu(D + bias) -> bf16 hi/lo planes
//   GELU=false: out = D + bias       -> fp32
// 256 threads = 8 warps (4m x 2n), warp tile 32x64, BK=32, cp.async 2-stage.
// ---------------------------------------------------------------------------
#define GS_ROW   80                    // smem row stride bytes (32 bf16 + 8 pad)
#define GS_TILE  (128 * GS_ROW)        // 10240 B
#define GS_STAGE (4 * GS_TILE)         // 40960 B  (A_hi, A_lo, B_hi, B_lo)
#define GS_TOTAL (2 * GS_STAGE)        // 81920 B

template <bool GELU>
__global__ __launch_bounds__(256, 1)
void hgemm_kernel(const __nv_bfloat16* __restrict__ Ah,
                  const __nv_bfloat16* __restrict__ Al,
                  const __nv_bfloat16* __restrict__ Bh,
                  const __nv_bfloat16* __restrict__ Bl,
                  const float* __restrict__ bias,
                  float* __restrict__ outF,
                  __nv_bfloat16* __restrict__ outHi,
                  __nv_bfloat16* __restrict__ outLo,
                  int K, int Ntot)
{
    extern __shared__ char smem[];
    const uint32_t sb = smem_u32(smem);

    const int tid = threadIdx.x;
    const int lid = tid & 31;
    const int wid = tid >> 5;
    const int wm  = wid & 3;        // 0..3 -> 32-row band
    const int wn  = wid >> 2;       // 0..1 -> 64-col band
    const int m0  = blockIdx.y * 128;
    const int n0  = blockIdx.x * 128;
    const int NC  = K >> 5;         // chunks of 32

    float acc[2][8][4] = {};

    // per-thread cp.async mapping: idx = tid + j*256 ; row = idx/4 ; seg = idx%4
    const int r0a = tid >> 2, sg = (tid & 3);

    // ldmatrix lane base offsets (within a stage)
    //   A: row = wm*32 + (lid%16), col byte = (lid/16)*16  (+ mi*16 rows, + ks*32)
    const uint32_t a_lane = (uint32_t)((wm * 32 + (lid & 15)) * GS_ROW + (lid >> 4) * 16);
    //   B: row = wn*64 + (lid/16)*8 + (lid%8), col byte = ((lid>>3)&1)*16 (+ nb*16 rows, + ks*32)
    const uint32_t b_lane = (uint32_t)((wn * 64 + ((lid >> 4) << 3) + (lid & 7)) * GS_ROW
                                       + ((lid >> 3) & 1) * 16);

    // ---- chunk loader ----
    auto load_chunk = [&](int i) {
        const uint32_t s0 = sb + (uint32_t)(i & 1) * GS_STAGE;
        const int k0 = i << 5;
        #pragma unroll
        for (int j = 0; j < 2; j++) {
            int row = r0a + j * 64;
            uint32_t so = s0 + (uint32_t)(row * GS_ROW + sg * 16);
            size_t ga = (size_t)(m0 + row) * K + k0 + sg * 8;
            size_t gb = (size_t)(n0 + row) * K + k0 + sg * 8;
            cp_async16(so,               Ah + ga);
            cp_async16(so + GS_TILE,     Al + ga);
            cp_async16(so + 2 * GS_TILE, Bh + gb);
            cp_async16(so + 3 * GS_TILE, Bl + gb);
        }
        cp_commit();
    };

    load_chunk(0);

    for (int i = 0; i < NC; i++) {
        if (i > 0) __syncthreads();          // stage (i+1)&1 free to overwrite
        if (i + 1 < NC) { load_chunk(i + 1); cp_wait1(); }
        else            { cp_wait0(); }
        __syncthreads();

        const uint32_t s0 = sb + (uint32_t)(i & 1) * GS_STAGE;
        const uint32_t aB = s0 + a_lane;
        const uint32_t bB = s0 + 2 * GS_TILE + b_lane;

        #pragma unroll
        for (int ks = 0; ks < 2; ks++) {
            uint32_t ah[2][4], al[2][4];
            ldmx4(ah[0], aB + ks * 32);
            ldmx4(ah[1], aB + 16 * GS_ROW + ks * 32);
            ldmx4(al[0], aB + GS_TILE + ks * 32);
            ldmx4(al[1], aB + GS_TILE + 16 * GS_ROW + ks * 32);

            #pragma unroll
            for (int nb = 0; nb < 4; nb++) {
                uint32_t bh[4], bl[4];
                ldmx4(bh, bB + nb * 16 * GS_ROW + ks * 32);
                ldmx4(bl, bB + GS_TILE + nb * 16 * GS_ROW + ks * 32);

                #pragma unroll
                for (int h = 0; h < 2; h++) {      // two n8 atoms per x4
                    #pragma unroll
                    for (int mi = 0; mi < 2; mi++) {
                        float* d = acc[mi][nb * 2 + h];
                        mma_bf16(d, ah[mi], bh[2 * h], bh[2 * h + 1]);  // hi*hi
                        mma_bf16(d, ah[mi], bl[2 * h], bl[2 * h + 1]);  // hi*lo
                        mma_bf16(d, al[mi], bh[2 * h], bh[2 * h + 1]);  // lo*hi
                    }
                }
            }
        }
    }

    // ---- epilogue ----
    #pragma unroll
    for (int mi = 0; mi < 2; mi++) {
        int rbase = m0 + wm * 32 + mi * 16 + (lid >> 2);
        #pragma unroll
        for (int na = 0; na < 8; na++) {
            int col = n0 + wn * 64 + na * 8 + (lid & 3) * 2;
            float b0 = bias[col], b1 = bias[col + 1];
            #pragma unroll
            for (int h = 0; h < 2; h++) {
                int row = rbase + h * 8;
                float v0 = acc[mi][na][2 * h]     + b0;
                float v1 = acc[mi][na][2 * h + 1] + b1;
                size_t o = (size_t)row * Ntot + col;
                if (GELU) {
                    v0 = gelu_exact(v0);
                    v1 = gelu_exact(v1);
                    __nv_bfloat16 h0 = __float2bfloat16(v0);
                    __nv_bfloat16 h1 = __float2bfloat16(v1);
                    __nv_bfloat162 hv; hv.x = h0; hv.y = h1;
                    *(__nv_bfloat162*)(outHi + o) = hv;
                    __nv_bfloat162 lv;
                    lv.x = __float2bfloat16(v0 - __bfloat162float(h0));
                    lv.y = __float2bfloat16(v1 - __bfloat162float(h1));
                    *(__nv_bfloat162*)(outLo + o) = lv;
                } else {
                    float2 ov; ov.x = v0; ov.y = v1;
                    *(float2*)(outF + o) = ov;
                }
            }
        }
    }
}

// ---------------------------------------------------------------------------
// Launch
// ---------------------------------------------------------------------------
extern "C" void kernel_launch(void* const* d_in, const int* in_sizes, int n_in,
                              void* d_out, int out_size)
{
    const float* query     = (const float*)d_in[0];
    const float* images    = (const float*)d_in[1];
    const float* uv_w      = (const float*)d_in[2];
    const float* uv_b      = (const float*)d_in[3];
    const float* t_src_emb = (const float*)d_in[4];
    const float* t_tgt_emb = (const float*)d_in[5];
    const float* t_cam_emb = (const float*)d_in[6];
    const float* pm_w1     = (const float*)d_in[7];
    const float* pm_b1     = (const float*)d_in[8];
    const float* pm_w2     = (const float*)d_in[9];
    const float* pm_b2     = (const float*)d_in[10];
    const float* om_w1     = (const float*)d_in[11];
    const float* om_b1     = (const float*)d_in[12];
    const float* om_w2     = (const float*)d_in[13];
    const float* om_b2     = (const float*)d_in[14];
    float* out = (float*)d_out;

    const int M = in_sizes[0] / 5;                      // 32768
    const int Bb = in_sizes[1] / (3 * 48 * 256 * 256);  // 4
    const int nPerB = M / Bb;

    __nv_bfloat16 *x_hi, *x_lo, *h_hi, *h_lo, *w1_hi, *w1_lo, *w2_hi, *w2_lo;
    cudaGetSymbolAddress((void**)&x_hi,  g_x_hi);
    cudaGetSymbolAddress((void**)&x_lo,  g_x_lo);
    cudaGetSymbolAddress((void**)&h_hi,  g_h_hi);
    cudaGetSymbolAddress((void**)&h_lo,  g_h_lo);
    cudaGetSymbolAddress((void**)&w1_hi, g_w1_hi);
    cudaGetSymbolAddress((void**)&w1_lo, g_w1_lo);
    cudaGetSymbolAddress((void**)&w2_hi, g_w2_hi);
    cudaGetSymbolAddress((void**)&w2_lo, g_w2_lo);

    cudaFuncSetAttribute(hgemm_kernel<true>,
                         cudaFuncAttributeMaxDynamicSharedMemorySize, GS_TOTAL);
    cudaFuncSetAttribute(hgemm_kernel<false>,
                         cudaFuncAttributeMaxDynamicSharedMemorySize, GS_TOTAL);

    // Weight prep: [K][N] fp32 -> [N][K] bf16 hi/lo
    transpose_split_kernel<<<dim3(HID / 32, EMB / 32), dim3(32, 8)>>>(
        om_w1, w1_hi, w1_lo, EMB, HID);
    transpose_split_kernel<<<dim3(EMB / 32, HID / 32), dim3(32, 8)>>>(
        om_w2, w2_hi, w2_lo, HID, EMB);

    // Stage 1: embed -> x (bf16 hi/lo)
    embed_kernel<<<M / BQ, 256>>>(query, images, uv_w, uv_b,
                                  t_src_emb, t_tgt_emb, t_cam_emb,
                                  pm_w1, pm_b1, pm_w2, pm_b2,
                                  nPerB, x_hi, x_lo);

    // Stage 2: H = gelu(x @ w1 + b1) -> bf16 hi/lo
    hgemm_kernel<true><<<dim3(HID / 128, M / 128), 256, GS_TOTAL>>>(
        x_hi, x_lo, w1_hi, w1_lo, om_b1, nullptr, h_hi, h_lo, EMB, HID);

    // Stage 3: out = H @ w2 + b2 -> fp32
    hgemm_kernel<false><<<dim3(EMB / 128, M / 128), 256, GS_TOTAL>>>(
        h_hi, h_lo, w2_hi, w2_lo, om_b2, out, nullptr, nullptr, HID, EMB);
}

// round 10
// speedup vs baseline: 1.1939x; 1.1939x over previous
#include <cuda_runtime.h>
#include <cuda_bf16.h>
#include <math.h>
#include <stdint.h>

// ===========================================================================
// QueryEmbedding — embed (fused) + 2 bf16-split GEMMs via mma.sync (HMMA)
//   M=32768, EMB=768, HID=3072
//   GEMM: D = A_hi*B_hi + A_hi*B_lo + A_lo*B_hh   (bf16 in, fp32 accum)
//   tcgen05 unavailable (PTX target sm_103 lacks the 'a' features), so we use
//   mma.sync.m16n8k16 + ldmatrix + cp.async. R10 change: 2 CTAs/SM via
//   __launch_bounds__(256, 2) to fix the occupancy-bound tensor pipe (47.8%).
// ===========================================================================

#define M_TOTAL   32768
#define EMB       768
#define HID       3072
#define BQ        16

// ---------------- device scratch (no allocs allowed) ----------------------
__device__ __align__(16) __nv_bfloat16 g_x_hi [(size_t)M_TOTAL * EMB];
__device__ __align__(16) __nv_bfloat16 g_x_lo [(size_t)M_TOTAL * EMB];
__device__ __align__(16) __nv_bfloat16 g_h_hi [(size_t)M_TOTAL * HID];
__device__ __align__(16) __nv_bfloat16 g_h_lo [(size_t)M_TOTAL * HID];
__device__ __align__(16) __nv_bfloat16 g_w1_hi[(size_t)HID * EMB];   // [N=3072][K=768]
__device__ __align__(16) __nv_bfloat16 g_w1_lo[(size_t)HID * EMB];
__device__ __align__(16) __nv_bfloat16 g_w2_hi[(size_t)EMB * HID];   // [N=768][K=3072]
__device__ __align__(16) __nv_bfloat16 g_w2_lo[(size_t)EMB * HID];

__device__ __forceinline__ float gelu_exact(float x) {
    return 0.5f * x * (1.0f + erff(x * 0.70710678118654752440f));
}

// ---------------- PTX helpers ----------------------------------------------
__device__ __forceinline__ uint32_t smem_u32(const void* p) {
    uint32_t a;
    asm("{ .reg .u64 t; cvta.to.shared.u64 t, %1; cvt.u32.u64 %0, t; }"
        : "=r"(a) : "l"(p));
    return a;
}

__device__ __forceinline__ void cp_async16(uint32_t saddr, const void* gaddr) {
    asm volatile("cp.async.cg.shared.global [%0], [%1], 16;"
                 :: "r"(saddr), "l"(gaddr) : "memory");
}
__device__ __forceinline__ void cp_commit() {
    asm volatile("cp.async.commit_group;" ::: "memory");
}
__device__ __forceinline__ void cp_wait1() {
    asm volatile("cp.async.wait_group 1;" ::: "memory");
}
__device__ __forceinline__ void cp_wait0() {
    asm volatile("cp.async.wait_group 0;" ::: "memory");
}

__device__ __forceinline__ void ldmx4(uint32_t* r, uint32_t addr) {
    asm volatile("ldmatrix.sync.aligned.m8n8.x4.shared.b16 {%0,%1,%2,%3}, [%4];"
                 : "=r"(r[0]), "=r"(r[1]), "=r"(r[2]), "=r"(r[3]) : "r"(addr));
}

__device__ __forceinline__ void mma_bf16(float* d, const uint32_t* a,
                                         uint32_t b0, uint32_t b1) {
    asm volatile(
        "mma.sync.aligned.m16n8k16.row.col.f32.bf16.bf16.f32 "
        "{%0,%1,%2,%3}, {%4,%5,%6,%7}, {%8,%9}, {%0,%1,%2,%3};"
        : "+f"(d[0]), "+f"(d[1]), "+f"(d[2]), "+f"(d[3])
        : "r"(a[0]), "r"(a[1]), "r"(a[2]), "r"(a[3]), "r"(b0), "r"(b1));
}

// ---------------------------------------------------------------------------
// Embed kernel: x = token1..token5 per query, emitted as bf16 hi/lo
// ---------------------------------------------------------------------------
__global__ __launch_bounds__(256)
void embed_kernel(const float* __restrict__ query,
                  const float* __restrict__ images,
                  const float* __restrict__ uv_w,
                  const float* __restrict__ uv_b,
                  const float* __restrict__ t_src_emb,
                  const float* __restrict__ t_tgt_emb,
                  const float* __restrict__ t_cam_emb,
                  const float* __restrict__ pm_w1,
                  const float* __restrict__ pm_b1,
                  const float* __restrict__ pm_w2,
                  const float* __restrict__ pm_b2,
                  int nPerB,
                  __nv_bfloat16* __restrict__ x_hi,
                  __nv_bfloat16* __restrict__ x_lo)
{
    __shared__ float s_feat[BQ][40];
    __shared__ float s_patch[BQ][27];
    __shared__ float s_h1[BQ][108];
    __shared__ int   s_src[BQ], s_tgt[BQ], s_cam[BQ], s_x[BQ], s_y[BQ];

    const int tid = threadIdx.x;
    const int q0  = blockIdx.x * BQ;
    const float TWO_PI = 6.283185307179586476925f;

    if (tid < BQ) {
        const float* qp = query + (size_t)(q0 + tid) * 5;
        float u = fminf(fmaxf(qp[0], 0.0f), 1.0f);
        float v = fminf(fmaxf(qp[1], 0.0f), 1.0f);
        s_src[tid] = min(max(__float2int_rn(qp[2]), 0), 47);
        s_tgt[tid] = min(max(__float2int_rn(qp[3]), 0), 47);
        s_cam[tid] = min(max(__float2int_rn(qp[4]), 0), 47);
        s_x[tid] = min(max(__float2int_rn(u * 255.0f), 0), 255);
        s_y[tid] = min(max(__float2int_rn(v * 255.0f), 0), 255);

        float f = 1.0f;
        #pragma unroll
        for (int k = 0; k < 10; k++) {
            float au = u * f; au = (au - floorf(au)) * TWO_PI;
            float av = v * f; av = (av - floorf(av)) * TWO_PI;
            s_feat[tid][k]      = sinf(au);
            s_feat[tid][10 + k] = cosf(au);
            s_feat[tid][20 + k] = sinf(av);
            s_feat[tid][30 + k] = cosf(av);
            f *= 2.0f;
        }
    }
    __syncthreads();

    for (int i = tid; i < BQ * 27; i += 256) {
        int q  = i / 27;
        int r  = i - q * 27;
        int c  = r / 9;
        int rem = r - c * 9;
        int dy = rem / 3;
        int dx = rem - dy * 3;
        int yy = min(max(s_y[q] + dy - 1, 0), 255);
        int xx = min(max(s_x[q] + dx - 1, 0), 255);
        int b  = (q0 + q) / nPerB;
        size_t idx = (((size_t)(b * 3 + c) * 48 + (size_t)s_src[q]) * 65536)
                     + (size_t)yy * 256 + (size_t)xx;
        s_patch[q][r] = images[idx];
    }
    __syncthreads();

    for (int i = tid; i < BQ * 108; i += 256) {
        int q = i / 108;
        int j = i - q * 108;
        float acc = pm_b1[j];
        #pragma unroll
        for (int k = 0; k < 27; k++)
            acc += s_patch[q][k] * pm_w1[k * 108 + j];
        s_h1[q][j] = gelu_exact(acc);
    }
    __syncthreads();

    float acc[BQ][3];
    #pragma unroll
    for (int jj = 0; jj < 3; jj++) {
        int j = jj * 256 + tid;
        float base = uv_b[j] + pm_b2[j];
        #pragma unroll
        for (int q = 0; q < BQ; q++) {
            acc[q][jj] = base
                       + t_src_emb[s_src[q] * EMB + j]
                       + t_tgt_emb[s_tgt[q] * EMB + j]
                       + t_cam_emb[s_cam[q] * EMB + j];
        }
    }

    #pragma unroll 1
    for (int k = 0; k < 40; k++) {
        float w0 = uv_w[k * EMB + tid];
        float w1 = uv_w[k * EMB + 256 + tid];
        float w2 = uv_w[k * EMB + 512 + tid];
        #pragma unroll
        for (int q = 0; q < BQ; q++) {
            float f = s_feat[q][k];
            acc[q][0] += f * w0;
            acc[q][1] += f * w1;
            acc[q][2] += f * w2;
        }
    }

    #pragma unroll 1
    for (int k = 0; k < 108; k++) {
        float w0 = pm_w2[k * EMB + tid];
        float w1 = pm_w2[k * EMB + 256 + tid];
        float w2 = pm_w2[k * EMB + 512 + tid];
        #pragma unroll
        for (int q = 0; q < BQ; q++) {
            float h = s_h1[q][k];
            acc[q][0] += h * w0;
            acc[q][1] += h * w1;
            acc[q][2] += h * w2;
        }
    }

    #pragma unroll
    for (int q = 0; q < BQ; q++) {
        size_t base = (size_t)(q0 + q) * EMB;
        #pragma unroll
        for (int jj = 0; jj < 3; jj++) {
            float v = acc[q][jj];
            __nv_bfloat16 h = __float2bfloat16(v);
            x_hi[base + jj * 256 + tid] = h;
            x_lo[base + jj * 256 + tid] = __float2bfloat16(v - __bfloat162float(h));
        }
    }
}

// ---------------------------------------------------------------------------
// Weight transpose + hi/lo split:  in[K][N] fp32  ->  out[N][K] bf16 hi/lo
// ---------------------------------------------------------------------------
__global__ __launch_bounds__(256)
void transpose_split_kernel(const float* __restrict__ in,
                            __nv_bfloat16* __restrict__ hi,
                            __nv_bfloat16* __restrict__ lo,
                            int K, int N)
{
    __shared__ float t[32][33];
    const int n0 = blockIdx.x * 32;
    const int k0 = blockIdx.y * 32;
    const int tx = threadIdx.x;   // 0..31
    const int ty = threadIdx.y;   // 0..7

    #pragma unroll
    for (int r = ty; r < 32; r += 8)
        t[r][tx] = in[(size_t)(k0 + r) * N + n0 + tx];
    __syncthreads();

    #pragma unroll
    for (int r = ty; r < 32; r += 8) {
        float v = t[tx][r];  // in[k0+tx][n0+r]
        __nv_bfloat16 h = __float2bfloat16(v);
        size_t o = (size_t)(n0 + r) * K + k0 + tx;
        hi[o] = h;
        lo[o] = __float2bfloat16(v - __bfloat162float(h));
    }
}

// ---------------------------------------------------------------------------
// HMMA GEMM:  C(128x128 tile) = A(MxK) @ B^T(NtotxK), bf16 3-term split.
//   A, B stored row-major [rows][K] bf16 (hi and lo planes).
//   GELU=true : out = gelu(D + bias) -> bf16 hi/lo planes
//   GELU=false: out = D + bias       -> fp32
// 256 threads = 8 warps (4m x 2n), warp tile 32x64, BK=32, cp.async 2-stage,
// 2 CTAs/SM (register-capped at 128) for latency hiding.
// ---------------------------------------------------------------------------
#define GS_ROW   80                    // smem row stride bytes (32 bf16 + 8 pad)
#define GS_TILE  (128 * GS_ROW)        // 10240 B
#define GS_STAGE (4 * GS_TILE)         // 40960 B  (A_hi, A_lo, B_hi, B_lo)
#define GS_TOTAL (2 * GS_STAGE)        // 81920 B

template <bool GELU>
__global__ __launch_bounds__(256, 2)
void hgemm_kernel(const __nv_bfloat16* __restrict__ Ah,
                  const __nv_bfloat16* __restrict__ Al,
                  const __nv_bfloat16* __restrict__ Bh,
                  const __nv_bfloat16* __restrict__ Bl,
                  const float* __restrict__ bias,
                  float* __restrict__ outF,
                  __nv_bfloat16* __restrict__ outHi,
                  __nv_bfloat16* __restrict__ outLo,
                  int K, int Ntot)
{
    extern __shared__ char smem[];
    const uint32_t sb = smem_u32(smem);

    const int tid = threadIdx.x;
    const int lid = tid & 31;
    const int wid = tid >> 5;
    const int wm  = wid & 3;        // 0..3 -> 32-row band
    const int wn  = wid >> 2;       // 0..1 -> 64-col band
    const int m0  = blockIdx.y * 128;
    const int n0  = blockIdx.x * 128;
    const int NC  = K >> 5;         // chunks of 32

    float acc[2][8][4] = {};

    // per-thread cp.async mapping: idx = tid + j*256 ; row = idx/4 ; seg = idx%4
    const int r0a = tid >> 2, sg = (tid & 3);

    // ldmatrix lane base offsets (within a stage)
    const uint32_t a_lane = (uint32_t)((wm * 32 + (lid & 15)) * GS_ROW + (lid >> 4) * 16);
    const uint32_t b_lane = (uint32_t)((wn * 64 + ((lid >> 4) << 3) + (lid & 7)) * GS_ROW
                                       + ((lid >> 3) & 1) * 16);

    // ---- chunk loader ----
    auto load_chunk = [&](int i) {
        const uint32_t s0 = sb + (uint32_t)(i & 1) * GS_STAGE;
        const int k0 = i << 5;
        #pragma unroll
        for (int j = 0; j < 2; j++) {
            int row = r0a + j * 64;
            uint32_t so = s0 + (uint32_t)(row * GS_ROW + sg * 16);
            size_t ga = (size_t)(m0 + row) * K + k0 + sg * 8;
            size_t gb = (size_t)(n0 + row) * K + k0 + sg * 8;
            cp_async16(so,               Ah + ga);
            cp_async16(so + GS_TILE,     Al + ga);
            cp_async16(so + 2 * GS_TILE, Bh + gb);
            cp_async16(so + 3 * GS_TILE, Bl + gb);
        }
        cp_commit();
    };

    load_chunk(0);

    for (int i = 0; i < NC; i++) {
        if (i > 0) __syncthreads();          // stage (i+1)&1 free to overwrite
        if (i + 1 < NC) { load_chunk(i + 1); cp_wait1(); }
        else            { cp_wait0(); }
        __syncthreads();

        const uint32_t s0 = sb + (uint32_t)(i & 1) * GS_STAGE;
        const uint32_t aB = s0 + a_lane;
        const uint32_t bB = s0 + 2 * GS_TILE + b_lane;

        #pragma unroll
        for (int ks = 0; ks < 2; ks++) {
            uint32_t ah[2][4], al[2][4];
            ldmx4(ah[0], aB + ks * 32);
            ldmx4(ah[1], aB + 16 * GS_ROW + ks * 32);
            ldmx4(al[0], aB + GS_TILE + ks * 32);
            ldmx4(al[1], aB + GS_TILE + 16 * GS_ROW + ks * 32);

            #pragma unroll
            for (int nb = 0; nb < 4; nb++) {
                uint32_t bh[4], bl[4];
                ldmx4(bh, bB + nb * 16 * GS_ROW + ks * 32);
                ldmx4(bl, bB + GS_TILE + nb * 16 * GS_ROW + ks * 32);

                #pragma unroll
                for (int h = 0; h < 2; h++) {      // two n8 atoms per x4
                    #pragma unroll
                    for (int mi = 0; mi < 2; mi++) {
                        float* d = acc[mi][nb * 2 + h];
                        mma_bf16(d, ah[mi], bh[2 * h], bh[2 * h + 1]);  // hi*hi
                        mma_bf16(d, ah[mi], bl[2 * h], bl[2 * h + 1]);  // hi*lo
                        mma_bf16(d, al[mi], bh[2 * h], bh[2 * h + 1]);  // lo*hi
                    }
                }
            }
        }
    }

    // ---- epilogue ----
    #pragma unroll
    for (int mi = 0; mi < 2; mi++) {
        int rbase = m0 + wm * 32 + mi * 16 + (lid >> 2);
        #pragma unroll
        for (int na = 0; na < 8; na++) {
            int col = n0 + wn * 64 + na * 8 + (lid & 3) * 2;
            float b0 = bias[col], b1 = bias[col + 1];
            #pragma unroll
            for (int h = 0; h < 2; h++) {
                int row = rbase + h * 8;
                float v0 = acc[mi][na][2 * h]     + b0;
                float v1 = acc[mi][na][2 * h + 1] + b1;
                size_t o = (size_t)row * Ntot + col;
                if (GELU) {
                    v0 = gelu_exact(v0);
                    v1 = gelu_exact(v1);
                    __nv_bfloat16 h0 = __float2bfloat16(v0);
                    __nv_bfloat16 h1 = __float2bfloat16(v1);
                    __nv_bfloat162 hv; hv.x = h0; hv.y = h1;
                    *(__nv_bfloat162*)(outHi + o) = hv;
                    __nv_bfloat162 lv;
                    lv.x = __float2bfloat16(v0 - __bfloat162float(h0));
                    lv.y = __float2bfloat16(v1 - __bfloat162float(h1));
                    *(__nv_bfloat162*)(outLo + o) = lv;
                } else {
                    float2 ov; ov.x = v0; ov.y = v1;
                    *(float2*)(outF + o) = ov;
                }
            }
        }
    }
}

// ---------------------------------------------------------------------------
// Launch
// ---------------------------------------------------------------------------
extern "C" void kernel_launch(void* const* d_in, const int* in_sizes, int n_in,
                              void* d_out, int out_size)
{
    const float* query     = (const float*)d_in[0];
    const float* images    = (const float*)d_in[1];
    const float* uv_w      = (const float*)d_in[2];
    const float* uv_b      = (const float*)d_in[3];
    const float* t_src_emb = (const float*)d_in[4];
    const float* t_tgt_emb = (const float*)d_in[5];
    const float* t_cam_emb = (const float*)d_in[6];
    const float* pm_w1     = (const float*)d_in[7];
    const float* pm_b1     = (const float*)d_in[8];
    const float* pm_w2     = (const float*)d_in[9];
    const float* pm_b2     = (const float*)d_in[10];
    const float* om_w1     = (const float*)d_in[11];
    const float* om_b1     = (const float*)d_in[12];
    const float* om_w2     = (const float*)d_in[13];
    const float* om_b2     = (const float*)d_in[14];
    float* out = (float*)d_out;

    const int M = in_sizes[0] / 5;                      // 32768
    const int Bb = in_sizes[1] / (3 * 48 * 256 * 256);  // 4
    const int nPerB = M / Bb;

    __nv_bfloat16 *x_hi, *x_lo, *h_hi, *h_lo, *w1_hi, *w1_lo, *w2_hi, *w2_lo;
    cudaGetSymbolAddress((void**)&x_hi,  g_x_hi);
    cudaGetSymbolAddress((void**)&x_lo,  g_x_lo);
    cudaGetSymbolAddress((void**)&h_hi,  g_h_hi);
    cudaGetSymbolAddress((void**)&h_lo,  g_h_lo);
    cudaGetSymbolAddress((void**)&w1_hi, g_w1_hi);
    cudaGetSymbolAddress((void**)&w1_lo, g_w1_lo);
    cudaGetSymbolAddress((void**)&w2_hi, g_w2_hi);
    cudaGetSymbolAddress((void**)&w2_lo, g_w2_lo);

    cudaFuncSetAttribute(hgemm_kernel<true>,
                         cudaFuncAttributeMaxDynamicSharedMemorySize, GS_TOTAL);
    cudaFuncSetAttribute(hgemm_kernel<false>,
                         cudaFuncAttributeMaxDynamicSharedMemorySize, GS_TOTAL);

    // Weight prep: [K][N] fp32 -> [N][K] bf16 hi/lo
    transpose_split_kernel<<<dim3(HID / 32, EMB / 32), dim3(32, 8)>>>(
        om_w1, w1_hi, w1_lo, EMB, HID);
    transpose_split_kernel<<<dim3(EMB / 32, HID / 32), dim3(32, 8)>>>(
        om_w2, w2_hi, w2_lo, HID, EMB);

    // Stage 1: embed -> x (bf16 hi/lo)
    embed_kernel<<<M / BQ, 256>>>(query, images, uv_w, uv_b,
                                  t_src_emb, t_tgt_emb, t_cam_emb,
                                  pm_w1, pm_b1, pm_w2, pm_b2,
                                  nPerB, x_hi, x_lo);

    // Stage 2: H = gelu(x @ w1 + b1) -> bf16 hi/lo
    hgemm_kernel<true><<<dim3(HID / 128, M / 128), 256, GS_TOTAL>>>(
        x_hi, x_lo, w1_hi, w1_lo, om_b1, nullptr, h_hi, h_lo, EMB, HID);

    // Stage 3: out = H @ w2 + b2 -> fp32
    hgemm_kernel<false><<<dim3(EMB / 128, M / 128), 256, GS_TOTAL>>>(
        h_hi, h_lo, w2_hi, w2_lo, om_b2, out, nullptr, nullptr, HID, EMB);
}

// round 11
// speedup vs baseline: 1.1951x; 1.0010x over previous
#include <cuda_runtime.h>
#include <cuda_bf16.h>
#include <math.h>
#include <stdint.h>

// ===========================================================================
// QueryEmbedding — embed (fused) + 2 bf16-split GEMMs via mma.sync (HMMA)
//   M=32768, EMB=768, HID=3072
//   GEMM: D = A_hi*B_hi + A_hi*B_lo + A_lo*B_hh   (bf16 in, fp32 accum)
//   tcgen05 unavailable (PTX target sm_103 lacks the 'a' features), so we use
//   mma.sync.m16n8k16 + ldmatrix + cp.async. R10 change: 2 CTAs/SM via
//   __launch_bounds__(256, 2) to fix the occupancy-bound tensor pipe (47.8%).
// ===========================================================================

#define M_TOTAL   32768
#define EMB       768
#define HID       3072
#define BQ        16

// ---------------- device scratch (no allocs allowed) ----------------------
__device__ __align__(16) __nv_bfloat16 g_x_hi [(size_t)M_TOTAL * EMB];
__device__ __align__(16) __nv_bfloat16 g_x_lo [(size_t)M_TOTAL * EMB];
__device__ __align__(16) __nv_bfloat16 g_h_hi [(size_t)M_TOTAL * HID];
__device__ __align__(16) __nv_bfloat16 g_h_lo [(size_t)M_TOTAL * HID];
__device__ __align__(16) __nv_bfloat16 g_w1_hi[(size_t)HID * EMB];   // [N=3072][K=768]
__device__ __align__(16) __nv_bfloat16 g_w1_lo[(size_t)HID * EMB];
__device__ __align__(16) __nv_bfloat16 g_w2_hi[(size_t)EMB * HID];   // [N=768][K=3072]
__device__ __align__(16) __nv_bfloat16 g_w2_lo[(size_t)EMB * HID];

__device__ __forceinline__ float gelu_exact(float x) {
    return 0.5f * x * (1.0f + erff(x * 0.70710678118654752440f));
}

// ---------------- PTX helpers ----------------------------------------------
__device__ __forceinline__ uint32_t smem_u32(const void* p) {
    uint32_t a;
    asm("{ .reg .u64 t; cvta.to.shared.u64 t, %1; cvt.u32.u64 %0, t; }"
        : "=r"(a) : "l"(p));
    return a;
}

__device__ __forceinline__ void cp_async16(uint32_t saddr, const void* gaddr) {
    asm volatile("cp.async.cg.shared.global [%0], [%1], 16;"
                 :: "r"(saddr), "l"(gaddr) : "memory");
}
__device__ __forceinline__ void cp_commit() {
    asm volatile("cp.async.commit_group;" ::: "memory");
}
__device__ __forceinline__ void cp_wait1() {
    asm volatile("cp.async.wait_group 1;" ::: "memory");
}
__device__ __forceinline__ void cp_wait0() {
    asm volatile("cp.async.wait_group 0;" ::: "memory");
}

__device__ __forceinline__ void ldmx4(uint32_t* r, uint32_t addr) {
    asm volatile("ldmatrix.sync.aligned.m8n8.x4.shared.b16 {%0,%1,%2,%3}, [%4];"
                 : "=r"(r[0]), "=r"(r[1]), "=r"(r[2]), "=r"(r[3]) : "r"(addr));
}

__device__ __forceinline__ void mma_bf16(float* d, const uint32_t* a,
                                         uint32_t b0, uint32_t b1) {
    asm volatile(
        "mma.sync.aligned.m16n8k16.row.col.f32.bf16.bf16.f32 "
        "{%0,%1,%2,%3}, {%4,%5,%6,%7}, {%8,%9}, {%0,%1,%2,%3};"
        : "+f"(d[0]), "+f"(d[1]), "+f"(d[2]), "+f"(d[3])
        : "r"(a[0]), "r"(a[1]), "r"(a[2]), "r"(a[3]), "r"(b0), "r"(b1));
}

// ---------------------------------------------------------------------------
// Embed kernel: x = token1..token5 per query, emitted as bf16 hi/lo
// ---------------------------------------------------------------------------
__global__ __launch_bounds__(256)
void embed_kernel(const float* __restrict__ query,
                  const float* __restrict__ images,
                  const float* __restrict__ uv_w,
                  const float* __restrict__ uv_b,
                  const float* __restrict__ t_src_emb,
                  const float* __restrict__ t_tgt_emb,
                  const float* __restrict__ t_cam_emb,
                  const float* __restrict__ pm_w1,
                  const float* __restrict__ pm_b1,
                  const float* __restrict__ pm_w2,
                  const float* __restrict__ pm_b2,
                  int nPerB,
                  __nv_bfloat16* __restrict__ x_hi,
                  __nv_bfloat16* __restrict__ x_lo)
{
    __shared__ float s_feat[BQ][40];
    __shared__ float s_patch[BQ][27];
    __shared__ float s_h1[BQ][108];
    __shared__ int   s_src[BQ], s_tgt[BQ], s_cam[BQ], s_x[BQ], s_y[BQ];

    const int tid = threadIdx.x;
    const int q0  = blockIdx.x * BQ;
    const float TWO_PI = 6.283185307179586476925f;

    if (tid < BQ) {
        const float* qp = query + (size_t)(q0 + tid) * 5;
        float u = fminf(fmaxf(qp[0], 0.0f), 1.0f);
        float v = fminf(fmaxf(qp[1], 0.0f), 1.0f);
        s_src[tid] = min(max(__float2int_rn(qp[2]), 0), 47);
        s_tgt[tid] = min(max(__float2int_rn(qp[3]), 0), 47);
        s_cam[tid] = min(max(__float2int_rn(qp[4]), 0), 47);
        s_x[tid] = min(max(__float2int_rn(u * 255.0f), 0), 255);
        s_y[tid] = min(max(__float2int_rn(v * 255.0f), 0), 255);

        float f = 1.0f;
        #pragma unroll
        for (int k = 0; k < 10; k++) {
            float au = u * f; au = (au - floorf(au)) * TWO_PI;
            float av = v * f; av = (av - floorf(av)) * TWO_PI;
            s_feat[tid][k]      = sinf(au);
            s_feat[tid][10 + k] = cosf(au);
            s_feat[tid][20 + k] = sinf(av);
            s_feat[tid][30 + k] = cosf(av);
            f *= 2.0f;
        }
    }
    __syncthreads();

    for (int i = tid; i < BQ * 27; i += 256) {
        int q  = i / 27;
        int r  = i - q * 27;
        int c  = r / 9;
        int rem = r - c * 9;
        int dy = rem / 3;
        int dx = rem - dy * 3;
        int yy = min(max(s_y[q] + dy - 1, 0), 255);
        int xx = min(max(s_x[q] + dx - 1, 0), 255);
        int b  = (q0 + q) / nPerB;
        size_t idx = (((size_t)(b * 3 + c) * 48 + (size_t)s_src[q]) * 65536)
                     + (size_t)yy * 256 + (size_t)xx;
        s_patch[q][r] = images[idx];
    }
    __syncthreads();

    for (int i = tid; i < BQ * 108; i += 256) {
        int q = i / 108;
        int j = i - q * 108;
        float acc = pm_b1[j];
        #pragma unroll
        for (int k = 0; k < 27; k++)
            acc += s_patch[q][k] * pm_w1[k * 108 + j];
        s_h1[q][j] = gelu_exact(acc);
    }
    __syncthreads();

    float acc[BQ][3];
    #pragma unroll
    for (int jj = 0; jj < 3; jj++) {
        int j = jj * 256 + tid;
        float base = uv_b[j] + pm_b2[j];
        #pragma unroll
        for (int q = 0; q < BQ; q++) {
            acc[q][jj] = base
                       + t_src_emb[s_src[q] * EMB + j]
                       + t_tgt_emb[s_tgt[q] * EMB + j]
                       + t_cam_emb[s_cam[q] * EMB + j];
        }
    }

    #pragma unroll 1
    for (int k = 0; k < 40; k++) {
        float w0 = uv_w[k * EMB + tid];
        float w1 = uv_w[k * EMB + 256 + tid];
        float w2 = uv_w[k * EMB + 512 + tid];
        #pragma unroll
        for (int q = 0; q < BQ; q++) {
            float f = s_feat[q][k];
            acc[q][0] += f * w0;
            acc[q][1] += f * w1;
            acc[q][2] += f * w2;
        }
    }

    #pragma unroll 1
    for (int k = 0; k < 108; k++) {
        float w0 = pm_w2[k * EMB + tid];
        float w1 = pm_w2[k * EMB + 256 + tid];
        float w2 = pm_w2[k * EMB + 512 + tid];
        #pragma unroll
        for (int q = 0; q < BQ; q++) {
            float h = s_h1[q][k];
            acc[q][0] += h * w0;
            acc[q][1] += h * w1;
            acc[q][2] += h * w2;
        }
    }

    #pragma unroll
    for (int q = 0; q < BQ; q++) {
        size_t base = (size_t)(q0 + q) * EMB;
        #pragma unroll
        for (int jj = 0; jj < 3; jj++) {
            float v = acc[q][jj];
            __nv_bfloat16 h = __float2bfloat16(v);
            x_hi[base + jj * 256 + tid] = h;
            x_lo[base + jj * 256 + tid] = __float2bfloat16(v - __bfloat162float(h));
        }
    }
}

// ---------------------------------------------------------------------------
// Weight transpose + hi/lo split:  in[K][N] fp32  ->  out[N][K] bf16 hi/lo
// ---------------------------------------------------------------------------
__global__ __launch_bounds__(256)
void transpose_split_kernel(const float* __restrict__ in,
                            __nv_bfloat16* __restrict__ hi,
                            __nv_bfloat16* __restrict__ lo,
                            int K, int N)
{
    __shared__ float t[32][33];
    const int n0 = blockIdx.x * 32;
    const int k0 = blockIdx.y * 32;
    const int tx = threadIdx.x;   // 0..31
    const int ty = threadIdx.y;   // 0..7

    #pragma unroll
    for (int r = ty; r < 32; r += 8)
        t[r][tx] = in[(size_t)(k0 + r) * N + n0 + tx];
    __syncthreads();

    #pragma unroll
    for (int r = ty; r < 32; r += 8) {
        float v = t[tx][r];  // in[k0+tx][n0+r]
        __nv_bfloat16 h = __float2bfloat16(v);
        size_t o = (size_t)(n0 + r) * K + k0 + tx;
        hi[o] = h;
        lo[o] = __float2bfloat16(v - __bfloat162float(h));
    }
}

// ---------------------------------------------------------------------------
// HMMA GEMM:  C(128x128 tile) = A(MxK) @ B^T(NtotxK), bf16 3-term split.
//   A, B stored row-major [rows][K] bf16 (hi and lo planes).
//   GELU=true : out = gelu(D + bias) -> bf16 hi/lo planes
//   GELU=false: out = D + bias       -> fp32
// 256 threads = 8 warps (4m x 2n), warp tile 32x64, BK=32, cp.async 2-stage,
// 2 CTAs/SM (register-capped at 128) for latency hiding.
// ---------------------------------------------------------------------------
#define GS_ROW   80                    // smem row stride bytes (32 bf16 + 8 pad)
#define GS_TILE  (128 * GS_ROW)        // 10240 B
#define GS_STAGE (4 * GS_TILE)         // 40960 B  (A_hi, A_lo, B_hi, B_lo)
#define GS_TOTAL (2 * GS_STAGE)        // 81920 B

template <bool GELU>
__global__ __launch_bounds__(256, 2)
void hgemm_kernel(const __nv_bfloat16* __restrict__ Ah,
                  const __nv_bfloat16* __restrict__ Al,
                  const __nv_bfloat16* __restrict__ Bh,
                  const __nv_bfloat16* __restrict__ Bl,
                  const float* __restrict__ bias,
                  float* __restrict__ outF,
                  __nv_bfloat16* __restrict__ outHi,
                  __nv_bfloat16* __restrict__ outLo,
                  int K, int Ntot)
{
    extern __shared__ char smem[];
    const uint32_t sb = smem_u32(smem);

    const int tid = threadIdx.x;
    const int lid = tid & 31;
    const int wid = tid >> 5;
    const int wm  = wid & 3;        // 0..3 -> 32-row band
    const int wn  = wid >> 2;       // 0..1 -> 64-col band
    const int m0  = blockIdx.y * 128;
    const int n0  = blockIdx.x * 128;
    const int NC  = K >> 5;         // chunks of 32

    float acc[2][8][4] = {};

    // per-thread cp.async mapping: idx = tid + j*256 ; row = idx/4 ; seg = idx%4
    const int r0a = tid >> 2, sg = (tid & 3);

    // ldmatrix lane base offsets (within a stage)
    const uint32_t a_lane = (uint32_t)((wm * 32 + (lid & 15)) * GS_ROW + (lid >> 4) * 16);
    const uint32_t b_lane = (uint32_t)((wn * 64 + ((lid >> 4) << 3) + (lid & 7)) * GS_ROW
                                       + ((lid >> 3) & 1) * 16);

    // ---- chunk loader ----
    auto load_chunk = [&](int i) {
        const uint32_t s0 = sb + (uint32_t)(i & 1) * GS_STAGE;
        const int k0 = i << 5;
        #pragma unroll
        for (int j = 0; j < 2; j++) {
            int row = r0a + j * 64;
            uint32_t so = s0 + (uint32_t)(row * GS_ROW + sg * 16);
            size_t ga = (size_t)(m0 + row) * K + k0 + sg * 8;
            size_t gb = (size_t)(n0 + row) * K + k0 + sg * 8;
            cp_async16(so,               Ah + ga);
            cp_async16(so + GS_TILE,     Al + ga);
            cp_async16(so + 2 * GS_TILE, Bh + gb);
            cp_async16(so + 3 * GS_TILE, Bl + gb);
        }
        cp_commit();
    };

    load_chunk(0);

    for (int i = 0; i < NC; i++) {
        if (i > 0) __syncthreads();          // stage (i+1)&1 free to overwrite
        if (i + 1 < NC) { load_chunk(i + 1); cp_wait1(); }
        else            { cp_wait0(); }
        __syncthreads();

        const uint32_t s0 = sb + (uint32_t)(i & 1) * GS_STAGE;
        const uint32_t aB = s0 + a_lane;
        const uint32_t bB = s0 + 2 * GS_TILE + b_lane;

        #pragma unroll
        for (int ks = 0; ks < 2; ks++) {
            uint32_t ah[2][4], al[2][4];
            ldmx4(ah[0], aB + ks * 32);
            ldmx4(ah[1], aB + 16 * GS_ROW + ks * 32);
            ldmx4(al[0], aB + GS_TILE + ks * 32);
            ldmx4(al[1], aB + GS_TILE + 16 * GS_ROW + ks * 32);

            #pragma unroll
            for (int nb = 0; nb < 4; nb++) {
                uint32_t bh[4], bl[4];
                ldmx4(bh, bB + nb * 16 * GS_ROW + ks * 32);
                ldmx4(bl, bB + GS_TILE + nb * 16 * GS_ROW + ks * 32);

                #pragma unroll
                for (int h = 0; h < 2; h++) {      // two n8 atoms per x4
                    #pragma unroll
                    for (int mi = 0; mi < 2; mi++) {
                        float* d = acc[mi][nb * 2 + h];
                        mma_bf16(d, ah[mi], bh[2 * h], bh[2 * h + 1]);  // hi*hi
                        mma_bf16(d, ah[mi], bl[2 * h], bl[2 * h + 1]);  // hi*lo
                        mma_bf16(d, al[mi], bh[2 * h], bh[2 * h + 1]);  // lo*hi
                    }
                }
            }
        }
    }

    // ---- epilogue ----
    #pragma unroll
    for (int mi = 0; mi < 2; mi++) {
        int rbase = m0 + wm * 32 + mi * 16 + (lid >> 2);
        #pragma unroll
        for (int na = 0; na < 8; na++) {
            int col = n0 + wn * 64 + na * 8 + (lid & 3) * 2;
            float b0 = bias[col], b1 = bias[col + 1];
            #pragma unroll
            for (int h = 0; h < 2; h++) {
                int row = rbase + h * 8;
                float v0 = acc[mi][na][2 * h]     + b0;
                float v1 = acc[mi][na][2 * h + 1] + b1;
                size_t o = (size_t)row * Ntot + col;
                if (GELU) {
                    v0 = gelu_exact(v0);
                    v1 = gelu_exact(v1);
                    __nv_bfloat16 h0 = __float2bfloat16(v0);
                    __nv_bfloat16 h1 = __float2bfloat16(v1);
                    __nv_bfloat162 hv; hv.x = h0; hv.y = h1;
                    *(__nv_bfloat162*)(outHi + o) = hv;
                    __nv_bfloat162 lv;
                    lv.x = __float2bfloat16(v0 - __bfloat162float(h0));
                    lv.y = __float2bfloat16(v1 - __bfloat162float(h1));
                    *(__nv_bfloat162*)(outLo + o) = lv;
                } else {
                    float2 ov; ov.x = v0; ov.y = v1;
                    *(float2*)(outF + o) = ov;
                }
            }
        }
    }
}

// ---------------------------------------------------------------------------
// Launch
// ---------------------------------------------------------------------------
extern "C" void kernel_launch(void* const* d_in, const int* in_sizes, int n_in,
                              void* d_out, int out_size)
{
    const float* query     = (const float*)d_in[0];
    const float* images    = (const float*)d_in[1];
    const float* uv_w      = (const float*)d_in[2];
    const float* uv_b      = (const float*)d_in[3];
    const float* t_src_emb = (const float*)d_in[4];
    const float* t_tgt_emb = (const float*)d_in[5];
    const float* t_cam_emb = (const float*)d_in[6];
    const float* pm_w1     = (const float*)d_in[7];
    const float* pm_b1     = (const float*)d_in[8];
    const float* pm_w2     = (const float*)d_in[9];
    const float* pm_b2     = (const float*)d_in[10];
    const float* om_w1     = (const float*)d_in[11];
    const float* om_b1     = (const float*)d_in[12];
    const float* om_w2     = (const float*)d_in[13];
    const float* om_b2     = (const float*)d_in[14];
    float* out = (float*)d_out;

    const int M = in_sizes[0] / 5;                      // 32768
    const int Bb = in_sizes[1] / (3 * 48 * 256 * 256);  // 4
    const int nPerB = M / Bb;

    __nv_bfloat16 *x_hi, *x_lo, *h_hi, *h_lo, *w1_hi, *w1_lo, *w2_hi, *w2_lo;
    cudaGetSymbolAddress((void**)&x_hi,  g_x_hi);
    cudaGetSymbolAddress((void**)&x_lo,  g_x_lo);
    cudaGetSymbolAddress((void**)&h_hi,  g_h_hi);
    cudaGetSymbolAddress((void**)&h_lo,  g_h_lo);
    cudaGetSymbolAddress((void**)&w1_hi, g_w1_hi);
    cudaGetSymbolAddress((void**)&w1_lo, g_w1_lo);
    cudaGetSymbolAddress((void**)&w2_hi, g_w2_hi);
    cudaGetSymbolAddress((void**)&w2_lo, g_w2_lo);

    cudaFuncSetAttribute(hgemm_kernel<true>,
                         cudaFuncAttributeMaxDynamicSharedMemorySize, GS_TOTAL);
    cudaFuncSetAttribute(hgemm_kernel<false>,
                         cudaFuncAttributeMaxDynamicSharedMemorySize, GS_TOTAL);

    // Weight prep: [K][N] fp32 -> [N][K] bf16 hi/lo
    transpose_split_kernel<<<dim3(HID / 32, EMB / 32), dim3(32, 8)>>>(
        om_w1, w1_hi, w1_lo, EMB, HID);
    transpose_split_kernel<<<dim3(EMB / 32, HID / 32), dim3(32, 8)>>>(
        om_w2, w2_hi, w2_lo, HID, EMB);

    // Stage 1: embed -> x (bf16 hi/lo)
    embed_kernel<<<M / BQ, 256>>>(query, images, uv_w, uv_b,
                                  t_src_emb, t_tgt_emb, t_cam_emb,
                                  pm_w1, pm_b1, pm_w2, pm_b2,
                                  nPerB, x_hi, x_lo);

    // Stage 2: H = gelu(x @ w1 + b1) -> bf16 hi/lo
    hgemm_kernel<true><<<dim3(HID / 128, M / 128), 256, GS_TOTAL>>>(
        x_hi, x_lo, w1_hi, w1_lo, om_b1, nullptr, h_hi, h_lo, EMB, HID);

    // Stage 3: out = H @ w2 + b2 -> fp32
    hgemm_kernel<false><<<dim3(EMB / 128, M / 128), 256, GS_TOTAL>>>(
        h_hi, h_lo, w2_hi, w2_lo, om_b2, out, nullptr, nullptr, HID, EMB);
}